// round 14
// baseline (speedup 1.0000x reference)
#include <cuda_runtime.h>
#include <cuda_fp16.h>
#include <cstdint>
#include <math.h>

#define EMBED 1024
#define NHEAD 16
#define HDIM  64
#define BATCH 2
#define SEQQ  2048
#define SEQK  2048
#define MROWS (BATCH*SEQQ)   // 4096

// ----------------------------- scratch (no allocs allowed) -----------------
__device__ __half g_XqH[MROWS*EMBED], g_XqL[MROWS*EMBED];   // input splits (Q,K)
__device__ __half g_XkH[MROWS*EMBED], g_XkL[MROWS*EMBED];
__device__ __half g_Xv [MROWS*EMBED];                       // V input plain fp16
__device__ __half g_Wq[EMBED*EMBED], g_Wk[EMBED*EMBED];     // plain fp16 weights
__device__ __half g_Wv[EMBED*EMBED], g_Wo[EMBED*EMBED];
__device__ __half g_Q [MROWS*EMBED];                        // plain fp16 activations
__device__ __half g_K [MROWS*EMBED];
__device__ __half g_V [MROWS*EMBED];
__device__ __half g_A [MROWS*EMBED];                        // attn out, plain fp16

// ----------------------------- helpers -------------------------------------
__device__ __forceinline__ uint32_t smem_u32(const void* p) {
    uint32_t a;
    asm("{ .reg .u64 t; cvta.to.shared.u64 t, %1; cvt.u32.u64 %0, t; }" : "=r"(a) : "l"(p));
    return a;
}
#define CP_ASYNC16(dst, src) \
    asm volatile("cp.async.cg.shared.global [%0], [%1], 16;" :: "r"(dst), "l"(src))
#define CP_COMMIT() asm volatile("cp.async.commit_group;" ::: "memory")
#define CP_WAIT(n)  asm volatile("cp.async.wait_group %0;" :: "n"(n) : "memory")

__device__ __forceinline__ void ldsm_x4(uint32_t* r, uint32_t addr) {
    asm volatile("ldmatrix.sync.aligned.m8n8.x4.shared.b16 {%0,%1,%2,%3}, [%4];"
        : "=r"(r[0]), "=r"(r[1]), "=r"(r[2]), "=r"(r[3]) : "r"(addr));
}
__device__ __forceinline__ void ldsm_x4_t(uint32_t* r, uint32_t addr) {
    asm volatile("ldmatrix.sync.aligned.m8n8.x4.trans.shared.b16 {%0,%1,%2,%3}, [%4];"
        : "=r"(r[0]), "=r"(r[1]), "=r"(r[2]), "=r"(r[3]) : "r"(addr));
}
__device__ __forceinline__ void mma_f16(float* c, const uint32_t* a, const uint32_t* b) {
    asm volatile(
        "mma.sync.aligned.m16n8k16.row.col.f32.f16.f16.f32 "
        "{%0,%1,%2,%3}, {%4,%5,%6,%7}, {%8,%9}, {%0,%1,%2,%3};"
        : "+f"(c[0]), "+f"(c[1]), "+f"(c[2]), "+f"(c[3])
        : "r"(a[0]), "r"(a[1]), "r"(a[2]), "r"(a[3]), "r"(b[0]), "r"(b[1]));
}
__device__ __forceinline__ float ex2f(float x) {
    float y; asm("ex2.approx.f32 %0, %1;" : "=f"(y) : "f"(x)); return y;
}
__device__ __forceinline__ uint32_t ex2_h2(float x, float y) {
    uint32_t h;
    asm("{\n\t.reg .b32 t;\n\t"
        "cvt.rn.f16x2.f32 t, %2, %1;\n\t"
        "ex2.approx.f16x2 %0, t;\n\t}"
        : "=r"(h) : "f"(x), "f"(y));
    return h;
}
__device__ __forceinline__ uint32_t pack_h2(float x, float y) {
    __half2 h = __float22half2_rn(make_float2(x, y));
    return *reinterpret_cast<uint32_t*>(&h);
}
__device__ __forceinline__ void split_pair_h(float x, float y, uint32_t& hi, uint32_t& lo) {
    __half2 h = __float22half2_rn(make_float2(x, y));
    float hx = __low2float(h), hy = __high2float(h);
    __half2 l = __float22half2_rn(make_float2(x - hx, y - hy));
    hi = *reinterpret_cast<uint32_t*>(&h);
    lo = *reinterpret_cast<uint32_t*>(&l);
}

// ----------------------------- fused conversions (one launch) --------------
struct PrepJob { const float* src; __half* hi; __half* lo; int n4; };
__global__ void prep_kernel(PrepJob j0, PrepJob j1, PrepJob j2, PrepJob j3,
                            PrepJob j4, PrepJob j5, PrepJob j6)
{
    PrepJob j;
    switch (blockIdx.y) {
        case 0: j = j0; break; case 1: j = j1; break; case 2: j = j2; break;
        case 3: j = j3; break; case 4: j = j4; break; case 5: j = j5; break;
        default: j = j6; break;
    }
    int i = blockIdx.x * blockDim.x + threadIdx.x;
    if (i >= j.n4) return;
    float4 v = ((const float4*)j.src)[i];
    if (j.lo) {
        uint32_t h0, l0, h1, l1;
        split_pair_h(v.x, v.y, h0, l0);
        split_pair_h(v.z, v.w, h1, l1);
        ((uint32_t*)j.hi)[2*i] = h0; ((uint32_t*)j.hi)[2*i+1] = h1;
        ((uint32_t*)j.lo)[2*i] = l0; ((uint32_t*)j.lo)[2*i+1] = l1;
    } else {
        ((uint32_t*)j.hi)[2*i]   = pack_h2(v.x, v.y);
        ((uint32_t*)j.hi)[2*i+1] = pack_h2(v.z, v.w);
    }
}

// ----------------------------- HMMA GEMM (QKV batched, proven) -------------
struct GemmArgs {
    const __half *Ah, *Al, *Bh;
    const float* bias;
    float* Cf;
    __half *Ch;
    float scale;
};

#define GB_AOFF  0
#define GB_ALOFF 16384
#define GB_BOFF  32768
#define GB_STAGE 49152
#define GB_SMEM  (2*GB_STAGE) // 98304

__global__ void __launch_bounds__(256, 2) gemm_mma_kernel(
    GemmArgs ga0, GemmArgs ga1, GemmArgs ga2)
{
    const GemmArgs g = (blockIdx.z == 0) ? ga0 : (blockIdx.z == 1) ? ga1 : ga2;
    const bool two = (g.Al != nullptr);

    extern __shared__ char sm[];
    const uint32_t sbase = smem_u32(sm);
    const int tid = threadIdx.x;
    const int lane = tid & 31, wid = tid >> 5;
    const int wm = wid & 1, wn = wid >> 1;
    const int m0 = blockIdx.y * 128, n0 = blockIdx.x * 128;

    float acc[4][4][4];
#pragma unroll
    for (int i = 0; i < 4; i++)
#pragma unroll
        for (int j = 0; j < 4; j++)
#pragma unroll
            for (int k = 0; k < 4; k++) acc[i][j][k] = 0.f;

#define ISSUE_STAGE(buf, k0)                                                   \
    do {                                                                       \
        const uint32_t st = sbase + (buf) * GB_STAGE;                          \
        _Pragma("unroll")                                                      \
        for (int c = 0; c < 4; c++) {                                          \
            const int idx = c * 256 + tid;                                     \
            const int row = idx >> 3, seg = idx & 7;                           \
            uint32_t off = (uint32_t)(row * 128 + seg * 16);                   \
            off ^= ((off >> 3) & 0x70);                                        \
            const size_t gaa = (size_t)(m0 + row) * 1024 + (k0) + seg * 8;     \
            const size_t gbb = (size_t)(n0 + row) * 1024 + (k0) + seg * 8;     \
            CP_ASYNC16(st + GB_AOFF + off,  (const char*)(g.Ah + gaa));        \
            if (two) CP_ASYNC16(st + GB_ALOFF + off, (const char*)(g.Al + gaa)); \
            CP_ASYNC16(st + GB_BOFF + off,  (const char*)(g.Bh + gbb));        \
        }                                                                      \
    } while (0)

    ISSUE_STAGE(0, 0);
    CP_COMMIT();

    for (int s = 0; s < 16; s++) {
        if (s < 15) {
            ISSUE_STAGE((s + 1) & 1, (s + 1) * 64);
            CP_COMMIT();
            CP_WAIT(1);
        } else {
            CP_WAIT(0);
        }
        __syncthreads();

        const uint32_t st = sbase + (s & 1) * GB_STAGE;
#pragma unroll
        for (int ks = 0; ks < 4; ks++) {
            uint32_t ah[4][4], al[4][4], bh[2][4];
            const int ar = (lane & 7) + ((lane >> 3) & 1) * 8;
            const int ak = ks * 16 + ((lane >> 4) & 1) * 8;
#pragma unroll
            for (int mt = 0; mt < 4; mt++) {
                uint32_t off = (uint32_t)((wm * 64 + mt * 16 + ar) * 128 + ak * 2);
                off ^= ((off >> 3) & 0x70);
                ldsm_x4(ah[mt], st + GB_AOFF + off);
                if (two) ldsm_x4(al[mt], st + GB_ALOFF + off);
            }
            const int bn = (lane & 7) + ((lane >> 4) & 1) * 8;
            const int bk = ks * 16 + ((lane >> 3) & 1) * 8;
#pragma unroll
            for (int np = 0; np < 2; np++) {
                uint32_t off = (uint32_t)((wn * 32 + np * 16 + bn) * 128 + bk * 2);
                off ^= ((off >> 3) & 0x70);
                ldsm_x4(bh[np], st + GB_BOFF + off);
            }
#pragma unroll
            for (int mt = 0; mt < 4; mt++) {
#pragma unroll
                for (int nt = 0; nt < 4; nt++) {
                    const uint32_t* bhf = &bh[nt >> 1][(nt & 1) * 2];
                    mma_f16(acc[mt][nt], ah[mt], bhf);
                    if (two) mma_f16(acc[mt][nt], al[mt], bhf);
                }
            }
        }
        __syncthreads();
    }
#undef ISSUE_STAGE

#pragma unroll
    for (int mt = 0; mt < 4; mt++) {
        const int row = m0 + wm * 64 + mt * 16 + (lane >> 2);
#pragma unroll
        for (int nt = 0; nt < 4; nt++) {
            const int col = n0 + wn * 32 + nt * 8 + (lane & 3) * 2;
            const float bx = __ldg(g.bias + col), by = __ldg(g.bias + col + 1);
            float v0 = (acc[mt][nt][0] + bx) * g.scale;
            float v1 = (acc[mt][nt][1] + by) * g.scale;
            float v2 = (acc[mt][nt][2] + bx) * g.scale;
            float v3 = (acc[mt][nt][3] + by) * g.scale;
            if (g.Cf) {
                *(float2*)(g.Cf + (size_t)row * 1024 + col)       = make_float2(v0, v1);
                *(float2*)(g.Cf + (size_t)(row + 8) * 1024 + col) = make_float2(v2, v3);
            } else {
                *(uint32_t*)(g.Ch + (size_t)row * 1024 + col)       = pack_h2(v0, v1);
                *(uint32_t*)(g.Ch + (size_t)(row + 8) * 1024 + col) = pack_h2(v2, v3);
            }
        }
    }
}

// ----------------------------- HMMA GEMM, 1-term A (Wo), 3-stage ring ------
#define G1_AOFF  0
#define G1_BOFF  16384
#define G1_STAGE 32768
#define G1_SMEM  (3*G1_STAGE) // 98304 -> 2 CTAs/SM

__global__ void __launch_bounds__(256, 2) gemm1_mma_kernel(
    const __half* __restrict__ Ah, const __half* __restrict__ Bh,
    const float* __restrict__ bias, float* __restrict__ Cf)
{
    extern __shared__ char sm[];
    const uint32_t sbase = smem_u32(sm);
    const int tid = threadIdx.x;
    const int lane = tid & 31, wid = tid >> 5;
    const int wm = wid & 1, wn = wid >> 1;
    const int m0 = blockIdx.y * 128, n0 = blockIdx.x * 128;

    float acc[4][4][4];
#pragma unroll
    for (int i = 0; i < 4; i++)
#pragma unroll
        for (int j = 0; j < 4; j++)
#pragma unroll
            for (int k = 0; k < 4; k++) acc[i][j][k] = 0.f;

#define ISSUE_STAGE1(buf, k0)                                                  \
    do {                                                                       \
        const uint32_t st = sbase + (buf) * G1_STAGE;                          \
        _Pragma("unroll")                                                      \
        for (int c = 0; c < 4; c++) {                                          \
            const int idx = c * 256 + tid;                                     \
            const int row = idx >> 3, seg = idx & 7;                           \
            uint32_t off = (uint32_t)(row * 128 + seg * 16);                   \
            off ^= ((off >> 3) & 0x70);                                        \
            const size_t gaa = (size_t)(m0 + row) * 1024 + (k0) + seg * 8;     \
            const size_t gbb = (size_t)(n0 + row) * 1024 + (k0) + seg * 8;     \
            CP_ASYNC16(st + G1_AOFF + off, (const char*)(Ah + gaa));           \
            CP_ASYNC16(st + G1_BOFF + off, (const char*)(Bh + gbb));           \
        }                                                                      \
    } while (0)

    ISSUE_STAGE1(0, 0);
    CP_COMMIT();
    ISSUE_STAGE1(1, 64);
    CP_COMMIT();

    for (int s = 0; s < 16; s++) {
        if (s < 15) { CP_WAIT(1); } else { CP_WAIT(0); }
        __syncthreads();                 // single barrier per stage (3-ring)
        if (s < 14) {
            ISSUE_STAGE1((s + 2) % 3, (s + 2) * 64);
            CP_COMMIT();
        }

        const uint32_t st = sbase + (s % 3) * G1_STAGE;
#pragma unroll
        for (int ks = 0; ks < 4; ks++) {
            uint32_t ah[4][4], bh[2][4];
            const int ar = (lane & 7) + ((lane >> 3) & 1) * 8;
            const int ak = ks * 16 + ((lane >> 4) & 1) * 8;
#pragma unroll
            for (int mt = 0; mt < 4; mt++) {
                uint32_t off = (uint32_t)((wm * 64 + mt * 16 + ar) * 128 + ak * 2);
                off ^= ((off >> 3) & 0x70);
                ldsm_x4(ah[mt], st + G1_AOFF + off);
            }
            const int bn = (lane & 7) + ((lane >> 4) & 1) * 8;
            const int bk = ks * 16 + ((lane >> 3) & 1) * 8;
#pragma unroll
            for (int np = 0; np < 2; np++) {
                uint32_t off = (uint32_t)((wn * 32 + np * 16 + bn) * 128 + bk * 2);
                off ^= ((off >> 3) & 0x70);
                ldsm_x4(bh[np], st + G1_BOFF + off);
            }
#pragma unroll
            for (int mt = 0; mt < 4; mt++)
#pragma unroll
                for (int nt = 0; nt < 4; nt++)
                    mma_f16(acc[mt][nt], ah[mt], &bh[nt >> 1][(nt & 1) * 2]);
        }
    }
#undef ISSUE_STAGE1

#pragma unroll
    for (int mt = 0; mt < 4; mt++) {
        const int row = m0 + wm * 64 + mt * 16 + (lane >> 2);
#pragma unroll
        for (int nt = 0; nt < 4; nt++) {
            const int col = n0 + wn * 32 + nt * 8 + (lane & 3) * 2;
            const float bx = __ldg(bias + col), by = __ldg(bias + col + 1);
            *(float2*)(Cf + (size_t)row * 1024 + col) =
                make_float2(acc[mt][nt][0] + bx, acc[mt][nt][1] + by);
            *(float2*)(Cf + (size_t)(row + 8) * 1024 + col) =
                make_float2(acc[mt][nt][2] + bx, acc[mt][nt][3] + by);
        }
    }
}

// ----------------------------- MMA flash attention (fp16, 3-stage ring) ----
#define ATT_KOFF  0
#define ATT_VOFF  8192
#define ATT_STAGE 16384
#define ATT_QOFF  (3*ATT_STAGE)          // 49152
#define ATT_SMEM  (ATT_QOFF + 8192)      // 57344

__global__ void __launch_bounds__(128) attn_mma_kernel(
    const __half* __restrict__ Q,
    const __half* __restrict__ K,
    const __half* __restrict__ V,
    __half* __restrict__ A)
{
    extern __shared__ char sm[];
    const uint32_t sb = smem_u32(sm);
    const int tid = threadIdx.x;
    const int lane = tid & 31, wid = tid >> 5;
    const int b = blockIdx.z, h = blockIdx.y;
    const int q0 = blockIdx.x * 64;

    const size_t qbase = ((size_t)(b * SEQQ + q0)) * EMBED + h * HDIM;
#pragma unroll
    for (int c = 0; c < 4; c++) {
        const int idx = c * 128 + tid;
        const int row = idx >> 3, seg = idx & 7;
        uint32_t off = (uint32_t)(row * 128 + seg * 16);
        off ^= ((off >> 3) & 0x70);
        CP_ASYNC16(sb + ATT_QOFF + off,
                   (const char*)(Q + qbase + (size_t)row * 1024 + seg * 8));
    }
    CP_COMMIT();

#define ISSUE_KV(buf, kt)                                                      \
    do {                                                                       \
        const uint32_t st_ = sb + (buf) * ATT_STAGE;                           \
        const size_t kb = ((size_t)(b * SEQK + (kt) * 64)) * EMBED + h * HDIM; \
        _Pragma("unroll")                                                      \
        for (int c = 0; c < 4; c++) {                                          \
            const int idx = c * 128 + tid;                                     \
            const int row = idx >> 3, seg = idx & 7;                           \
            uint32_t off = (uint32_t)(row * 128 + seg * 16);                   \
            off ^= ((off >> 3) & 0x70);                                        \
            const size_t g = kb + (size_t)row * 1024 + seg * 8;                \
            CP_ASYNC16(st_ + ATT_KOFF + off, (const char*)(K + g));            \
            CP_ASYNC16(st_ + ATT_VOFF + off, (const char*)(V + g));            \
        }                                                                      \
    } while (0)

    ISSUE_KV(0, 0);
    CP_COMMIT();
    ISSUE_KV(1, 1);
    CP_COMMIT();

    // wait for Q only (2 KV groups still in flight), then load Q fragments
    CP_WAIT(2);
    __syncthreads();

    uint32_t qh[4][4];
    {
        const int ar = (lane & 7) + ((lane >> 3) & 1) * 8;
#pragma unroll
        for (int ks = 0; ks < 4; ks++) {
            const int ak = ks * 16 + ((lane >> 4) & 1) * 8;
            uint32_t off = (uint32_t)((wid * 16 + ar) * 128 + ak * 2);
            off ^= ((off >> 3) & 0x70);
            ldsm_x4(qh[ks], sb + ATT_QOFF + off);
        }
    }

    const uint32_t onefrag = ((lane >> 2) == 0) ? 0x3C003C00u : 0u;
    const uint32_t ones2[2] = { onefrag, onefrag };

    float m0 = -1e30f, m1 = -1e30f;
    float oacc[9][4];
#pragma unroll
    for (int nt = 0; nt < 9; nt++)
#pragma unroll
        for (int k = 0; k < 4; k++) oacc[nt][k] = 0.f;

    for (int kt = 0; kt < 32; kt++) {
        if (kt < 31) { CP_WAIT(1); } else { CP_WAIT(0); }
        __syncthreads();                 // single barrier per iteration (3-ring)
        if (kt < 30) {
            ISSUE_KV((kt + 2) % 3, kt + 2);
            CP_COMMIT();
        }
        const uint32_t st = sb + (kt % 3) * ATT_STAGE;

        float sacc[8][4];
#pragma unroll
        for (int nt = 0; nt < 8; nt++)
#pragma unroll
            for (int k = 0; k < 4; k++) sacc[nt][k] = 0.f;

#pragma unroll
        for (int ks = 0; ks < 4; ks++) {
            uint32_t kh[4][4];
            const int bn = (lane & 7) + ((lane >> 4) & 1) * 8;
            const int bk = ks * 16 + ((lane >> 3) & 1) * 8;
#pragma unroll
            for (int g = 0; g < 4; g++) {
                uint32_t off = (uint32_t)((g * 16 + bn) * 128 + bk * 2);
                off ^= ((off >> 3) & 0x70);
                ldsm_x4(kh[g], st + ATT_KOFF + off);
            }
#pragma unroll
            for (int nt = 0; nt < 8; nt++)
                mma_f16(sacc[nt], qh[ks], &kh[nt >> 1][(nt & 1) * 2]);
        }

        float mx0 = sacc[0][0], mx1 = sacc[0][2];
#pragma unroll
        for (int nt = 0; nt < 8; nt++) {
            mx0 = fmaxf(mx0, fmaxf(sacc[nt][0], sacc[nt][1]));
            mx1 = fmaxf(mx1, fmaxf(sacc[nt][2], sacc[nt][3]));
        }
        mx0 = fmaxf(mx0, __shfl_xor_sync(0xffffffffu, mx0, 1));
        mx0 = fmaxf(mx0, __shfl_xor_sync(0xffffffffu, mx0, 2));
        mx1 = fmaxf(mx1, __shfl_xor_sync(0xffffffffu, mx1, 1));
        mx1 = fmaxf(mx1, __shfl_xor_sync(0xffffffffu, mx1, 2));
        const bool nochange = (mx0 <= m0) && (mx1 <= m1);
        const float mn0 = fmaxf(m0, mx0), mn1 = fmaxf(m1, mx1);

        if (__all_sync(0xffffffffu, nochange)) {
            m0 = mn0; m1 = mn1;
        } else {
            const float a0 = ex2f(m0 - mn0), a1 = ex2f(m1 - mn1);
            m0 = mn0; m1 = mn1;
#pragma unroll
            for (int nt = 0; nt < 9; nt++) {
                oacc[nt][0] *= a0; oacc[nt][1] *= a0;
                oacc[nt][2] *= a1; oacc[nt][3] *= a1;
            }
        }

        uint32_t ph[4][4];
#pragma unroll
        for (int kf = 0; kf < 4; kf++) {
            ph[kf][0] = ex2_h2(sacc[2*kf][0]   - m0, sacc[2*kf][1]   - m0);
            ph[kf][1] = ex2_h2(sacc[2*kf][2]   - m1, sacc[2*kf][3]   - m1);
            ph[kf][2] = ex2_h2(sacc[2*kf+1][0] - m0, sacc[2*kf+1][1] - m0);
            ph[kf][3] = ex2_h2(sacc[2*kf+1][2] - m1, sacc[2*kf+1][3] - m1);
        }

#pragma unroll
        for (int ks = 0; ks < 4; ks++) {
            uint32_t vh[4][4];
            const int vk = ((lane >> 3) & 1) * 8 + (lane & 7);
            const int vd = ((lane >> 4) & 1) * 8;
#pragma unroll
            for (int dp = 0; dp < 4; dp++) {
                uint32_t off = (uint32_t)((ks * 16 + vk) * 128 + (dp * 16 + vd) * 2);
                off ^= ((off >> 3) & 0x70);
                ldsm_x4_t(vh[dp], st + ATT_VOFF + off);
            }
#pragma unroll
            for (int nt = 0; nt < 8; nt++)
                mma_f16(oacc[nt], ph[ks], &vh[nt >> 1][(nt & 1) * 2]);
            mma_f16(oacc[8], ph[ks], ones2);
        }
    }
#undef ISSUE_KV

    const int src = lane & ~3;
    const float l0 = __shfl_sync(0xffffffffu, oacc[8][0], src);
    const float l1 = __shfl_sync(0xffffffffu, oacc[8][2], src);

    const float inv0 = 1.f / l0, inv1 = 1.f / l1;
    const size_t row0 = (size_t)(b * SEQQ + q0 + wid * 16 + (lane >> 2));
    const size_t row1 = row0 + 8;
    const int colb = h * HDIM + (lane & 3) * 2;
#pragma unroll
    for (int nt = 0; nt < 8; nt++) {
        const int col = colb + nt * 8;
        *(uint32_t*)(A + row0 * 1024 + col) = pack_h2(oacc[nt][0] * inv0, oacc[nt][1] * inv0);
        *(uint32_t*)(A + row1 * 1024 + col) = pack_h2(oacc[nt][2] * inv1, oacc[nt][3] * inv1);
    }
}

// ---------------------------------------------------------------------------
extern "C" void kernel_launch(void* const* d_in, const int* in_sizes, int n_in,
                              void* d_out, int out_size)
{
    const float* Qin = (const float*)d_in[0];
    const float* Kin = (const float*)d_in[1];
    const float* Vin = (const float*)d_in[2];
    const float* Wq  = (const float*)d_in[3];
    const float* bq  = (const float*)d_in[4];
    const float* Wk  = (const float*)d_in[5];
    const float* bk  = (const float*)d_in[6];
    const float* Wv  = (const float*)d_in[7];
    const float* bv  = (const float*)d_in[8];
    const float* Wo  = (const float*)d_in[9];
    const float* bo  = (const float*)d_in[10];
    float* out = (float*)d_out;

    __half *xqH,*xqL,*xkH,*xkL,*xv;
    __half *wq,*wk,*wv,*wo;
    __half *q,*k,*v,*a;
    cudaGetSymbolAddress((void**)&xqH, g_XqH); cudaGetSymbolAddress((void**)&xqL, g_XqL);
    cudaGetSymbolAddress((void**)&xkH, g_XkH); cudaGetSymbolAddress((void**)&xkL, g_XkL);
    cudaGetSymbolAddress((void**)&xv,  g_Xv);
    cudaGetSymbolAddress((void**)&wq, g_Wq); cudaGetSymbolAddress((void**)&wk, g_Wk);
    cudaGetSymbolAddress((void**)&wv, g_Wv); cudaGetSymbolAddress((void**)&wo, g_Wo);
    cudaGetSymbolAddress((void**)&q,  g_Q);  cudaGetSymbolAddress((void**)&k,  g_K);
    cudaGetSymbolAddress((void**)&v,  g_V);  cudaGetSymbolAddress((void**)&a,  g_A);

    cudaFuncSetAttribute(gemm_mma_kernel,  cudaFuncAttributeMaxDynamicSharedMemorySize, GB_SMEM);
    cudaFuncSetAttribute(gemm1_mma_kernel, cudaFuncAttributeMaxDynamicSharedMemorySize, G1_SMEM);
    cudaFuncSetAttribute(attn_mma_kernel,  cudaFuncAttributeMaxDynamicSharedMemorySize, ATT_SMEM);

    const int nAct4 = MROWS * EMBED / 4;   // 1048576
    const int nW4   = EMBED * EMBED / 4;   // 262144

    PrepJob p0 = { Qin, xqH, xqL, nAct4 };
    PrepJob p1 = { Kin, xkH, xkL, nAct4 };
    PrepJob p2 = { Vin, xv, nullptr, nAct4 };
    PrepJob p3 = { Wq, wq, nullptr, nW4 };
    PrepJob p4 = { Wk, wk, nullptr, nW4 };
    PrepJob p5 = { Wv, wv, nullptr, nW4 };
    PrepJob p6 = { Wo, wo, nullptr, nW4 };
    dim3 prep_grid((nAct4 + 255) / 256, 7);
    prep_kernel<<<prep_grid, 256>>>(p0, p1, p2, p3, p4, p5, p6);

    const float qscale = 0.125f * 1.4426950408889634f;   // 1/sqrt(64) * log2(e)

    GemmArgs argQ = { xqH, xqL, wq, bq, nullptr, q, qscale };
    GemmArgs argK = { xkH, xkL, wk, bk, nullptr, k, 1.0f };
    GemmArgs argV = { xv,  nullptr, wv, bv, nullptr, v, 1.0f };

    dim3 qkv_grid(EMBED / 128, MROWS / 128, 3);   // (8, 32, 3)
    gemm_mma_kernel<<<qkv_grid, 256, GB_SMEM>>>(argQ, argK, argV);

    dim3 attn_grid(SEQQ / 64, NHEAD, BATCH);      // (32, 16, 2)
    attn_mma_kernel<<<attn_grid, 128, ATT_SMEM>>>(q, k, v, a);

    dim3 o_grid(EMBED / 128, MROWS / 128);        // (8, 32)
    gemm1_mma_kernel<<<o_grid, 256, G1_SMEM>>>(a, wo, bo, out);
}

// round 15
// speedup vs baseline: 1.0231x; 1.0231x over previous
#include <cuda_runtime.h>
#include <cuda_fp16.h>
#include <cstdint>
#include <math.h>

#define EMBED 1024
#define NHEAD 16
#define HDIM  64
#define BATCH 2
#define SEQQ  2048
#define SEQK  2048
#define MROWS (BATCH*SEQQ)   // 4096

// ----------------------------- scratch (no allocs allowed) -----------------
__device__ __half g_Xq [MROWS*EMBED];                       // Q input plain fp16
__device__ __half g_XkH[MROWS*EMBED], g_XkL[MROWS*EMBED];   // K input split
__device__ __half g_Xv [MROWS*EMBED];                       // V input plain fp16
__device__ __half g_Wq[EMBED*EMBED], g_Wk[EMBED*EMBED];     // plain fp16 weights
__device__ __half g_Wv[EMBED*EMBED], g_Wo[EMBED*EMBED];
__device__ __half g_Q [MROWS*EMBED];                        // plain fp16 activations
__device__ __half g_K [MROWS*EMBED];
__device__ __half g_V [MROWS*EMBED];
__device__ __half g_A [MROWS*EMBED];                        // attn out, plain fp16

// ----------------------------- helpers -------------------------------------
__device__ __forceinline__ uint32_t smem_u32(const void* p) {
    uint32_t a;
    asm("{ .reg .u64 t; cvta.to.shared.u64 t, %1; cvt.u32.u64 %0, t; }" : "=r"(a) : "l"(p));
    return a;
}
#define CP_ASYNC16(dst, src) \
    asm volatile("cp.async.cg.shared.global [%0], [%1], 16;" :: "r"(dst), "l"(src))
#define CP_COMMIT() asm volatile("cp.async.commit_group;" ::: "memory")
#define CP_WAIT(n)  asm volatile("cp.async.wait_group %0;" :: "n"(n) : "memory")

__device__ __forceinline__ void ldsm_x4(uint32_t* r, uint32_t addr) {
    asm volatile("ldmatrix.sync.aligned.m8n8.x4.shared.b16 {%0,%1,%2,%3}, [%4];"
        : "=r"(r[0]), "=r"(r[1]), "=r"(r[2]), "=r"(r[3]) : "r"(addr));
}
__device__ __forceinline__ void ldsm_x4_t(uint32_t* r, uint32_t addr) {
    asm volatile("ldmatrix.sync.aligned.m8n8.x4.trans.shared.b16 {%0,%1,%2,%3}, [%4];"
        : "=r"(r[0]), "=r"(r[1]), "=r"(r[2]), "=r"(r[3]) : "r"(addr));
}
__device__ __forceinline__ void mma_f16(float* c, const uint32_t* a, const uint32_t* b) {
    asm volatile(
        "mma.sync.aligned.m16n8k16.row.col.f32.f16.f16.f32 "
        "{%0,%1,%2,%3}, {%4,%5,%6,%7}, {%8,%9}, {%0,%1,%2,%3};"
        : "+f"(c[0]), "+f"(c[1]), "+f"(c[2]), "+f"(c[3])
        : "r"(a[0]), "r"(a[1]), "r"(a[2]), "r"(a[3]), "r"(b[0]), "r"(b[1]));
}
__device__ __forceinline__ float ex2f(float x) {
    float y; asm("ex2.approx.f32 %0, %1;" : "=f"(y) : "f"(x)); return y;
}
__device__ __forceinline__ uint32_t ex2_h2(float x, float y) {
    uint32_t h;
    asm("{\n\t.reg .b32 t;\n\t"
        "cvt.rn.f16x2.f32 t, %2, %1;\n\t"
        "ex2.approx.f16x2 %0, t;\n\t}"
        : "=r"(h) : "f"(x), "f"(y));
    return h;
}
__device__ __forceinline__ uint32_t pack_h2(float x, float y) {
    __half2 h = __float22half2_rn(make_float2(x, y));
    return *reinterpret_cast<uint32_t*>(&h);
}
__device__ __forceinline__ void split_pair_h(float x, float y, uint32_t& hi, uint32_t& lo) {
    __half2 h = __float22half2_rn(make_float2(x, y));
    float hx = __low2float(h), hy = __high2float(h);
    __half2 l = __float22half2_rn(make_float2(x - hx, y - hy));
    hi = *reinterpret_cast<uint32_t*>(&h);
    lo = *reinterpret_cast<uint32_t*>(&l);
}

// ----------------------------- fused conversions (one launch) --------------
struct PrepJob { const float* src; __half* hi; __half* lo; int n4; };
__global__ void prep_kernel(PrepJob j0, PrepJob j1, PrepJob j2, PrepJob j3,
                            PrepJob j4, PrepJob j5, PrepJob j6)
{
    PrepJob j;
    switch (blockIdx.y) {
        case 0: j = j0; break; case 1: j = j1; break; case 2: j = j2; break;
        case 3: j = j3; break; case 4: j = j4; break; case 5: j = j5; break;
        default: j = j6; break;
    }
    int i = blockIdx.x * blockDim.x + threadIdx.x;
    if (i >= j.n4) return;
    float4 v = ((const float4*)j.src)[i];
    if (j.lo) {
        uint32_t h0, l0, h1, l1;
        split_pair_h(v.x, v.y, h0, l0);
        split_pair_h(v.z, v.w, h1, l1);
        ((uint32_t*)j.hi)[2*i] = h0; ((uint32_t*)j.hi)[2*i+1] = h1;
        ((uint32_t*)j.lo)[2*i] = l0; ((uint32_t*)j.lo)[2*i+1] = l1;
    } else {
        ((uint32_t*)j.hi)[2*i]   = pack_h2(v.x, v.y);
        ((uint32_t*)j.hi)[2*i+1] = pack_h2(v.z, v.w);
    }
}

// ----------------------------- HMMA GEMM (QKV batched) ---------------------
// 2-term A if Al != nullptr, else 1-term. Branches are block-uniform.
struct GemmArgs {
    const __half *Ah, *Al, *Bh;
    const float* bias;
    float* Cf;
    __half *Ch;
    float scale;
};

#define GB_AOFF  0
#define GB_ALOFF 16384
#define GB_BOFF  32768
#define GB_STAGE 49152
#define GB_SMEM  (2*GB_STAGE) // 98304

__global__ void __launch_bounds__(256, 2) gemm_mma_kernel(
    GemmArgs ga0, GemmArgs ga1, GemmArgs ga2)
{
    const GemmArgs g = (blockIdx.z == 0) ? ga0 : (blockIdx.z == 1) ? ga1 : ga2;
    const bool two = (g.Al != nullptr);

    extern __shared__ char sm[];
    const uint32_t sbase = smem_u32(sm);
    const int tid = threadIdx.x;
    const int lane = tid & 31, wid = tid >> 5;
    const int wm = wid & 1, wn = wid >> 1;
    const int m0 = blockIdx.y * 128, n0 = blockIdx.x * 128;

    float acc[4][4][4];
#pragma unroll
    for (int i = 0; i < 4; i++)
#pragma unroll
        for (int j = 0; j < 4; j++)
#pragma unroll
            for (int k = 0; k < 4; k++) acc[i][j][k] = 0.f;

#define ISSUE_STAGE(buf, k0)                                                   \
    do {                                                                       \
        const uint32_t st = sbase + (buf) * GB_STAGE;                          \
        _Pragma("unroll")                                                      \
        for (int c = 0; c < 4; c++) {                                          \
            const int idx = c * 256 + tid;                                     \
            const int row = idx >> 3, seg = idx & 7;                           \
            uint32_t off = (uint32_t)(row * 128 + seg * 16);                   \
            off ^= ((off >> 3) & 0x70);                                        \
            const size_t gaa = (size_t)(m0 + row) * 1024 + (k0) + seg * 8;     \
            const size_t gbb = (size_t)(n0 + row) * 1024 + (k0) + seg * 8;     \
            CP_ASYNC16(st + GB_AOFF + off,  (const char*)(g.Ah + gaa));        \
            if (two) CP_ASYNC16(st + GB_ALOFF + off, (const char*)(g.Al + gaa)); \
            CP_ASYNC16(st + GB_BOFF + off,  (const char*)(g.Bh + gbb));        \
        }                                                                      \
    } while (0)

    ISSUE_STAGE(0, 0);
    CP_COMMIT();

    for (int s = 0; s < 16; s++) {
        if (s < 15) {
            ISSUE_STAGE((s + 1) & 1, (s + 1) * 64);
            CP_COMMIT();
            CP_WAIT(1);
        } else {
            CP_WAIT(0);
        }
        __syncthreads();

        const uint32_t st = sbase + (s & 1) * GB_STAGE;
#pragma unroll
        for (int ks = 0; ks < 4; ks++) {
            uint32_t ah[4][4], al[4][4], bh[2][4];
            const int ar = (lane & 7) + ((lane >> 3) & 1) * 8;
            const int ak = ks * 16 + ((lane >> 4) & 1) * 8;
#pragma unroll
            for (int mt = 0; mt < 4; mt++) {
                uint32_t off = (uint32_t)((wm * 64 + mt * 16 + ar) * 128 + ak * 2);
                off ^= ((off >> 3) & 0x70);
                ldsm_x4(ah[mt], st + GB_AOFF + off);
                if (two) ldsm_x4(al[mt], st + GB_ALOFF + off);
            }
            const int bn = (lane & 7) + ((lane >> 4) & 1) * 8;
            const int bk = ks * 16 + ((lane >> 3) & 1) * 8;
#pragma unroll
            for (int np = 0; np < 2; np++) {
                uint32_t off = (uint32_t)((wn * 32 + np * 16 + bn) * 128 + bk * 2);
                off ^= ((off >> 3) & 0x70);
                ldsm_x4(bh[np], st + GB_BOFF + off);
            }
#pragma unroll
            for (int mt = 0; mt < 4; mt++) {
#pragma unroll
                for (int nt = 0; nt < 4; nt++) {
                    const uint32_t* bhf = &bh[nt >> 1][(nt & 1) * 2];
                    mma_f16(acc[mt][nt], ah[mt], bhf);
                    if (two) mma_f16(acc[mt][nt], al[mt], bhf);
                }
            }
        }
        __syncthreads();
    }
#undef ISSUE_STAGE

#pragma unroll
    for (int mt = 0; mt < 4; mt++) {
        const int row = m0 + wm * 64 + mt * 16 + (lane >> 2);
#pragma unroll
        for (int nt = 0; nt < 4; nt++) {
            const int col = n0 + wn * 32 + nt * 8 + (lane & 3) * 2;
            const float bx = __ldg(g.bias + col), by = __ldg(g.bias + col + 1);
            float v0 = (acc[mt][nt][0] + bx) * g.scale;
            float v1 = (acc[mt][nt][1] + by) * g.scale;
            float v2 = (acc[mt][nt][2] + bx) * g.scale;
            float v3 = (acc[mt][nt][3] + by) * g.scale;
            if (g.Cf) {
                *(float2*)(g.Cf + (size_t)row * 1024 + col)       = make_float2(v0, v1);
                *(float2*)(g.Cf + (size_t)(row + 8) * 1024 + col) = make_float2(v2, v3);
            } else {
                *(uint32_t*)(g.Ch + (size_t)row * 1024 + col)       = pack_h2(v0, v1);
                *(uint32_t*)(g.Ch + (size_t)(row + 8) * 1024 + col) = pack_h2(v2, v3);
            }
        }
    }
}

// ----------------------------- HMMA GEMM, 1-term A (Wo), 2-stage -----------
#define G1_AOFF  0
#define G1_BOFF  16384
#define G1_STAGE 32768
#define G1_SMEM  (2*G1_STAGE) // 65536

__global__ void __launch_bounds__(256, 2) gemm1_mma_kernel(
    const __half* __restrict__ Ah, const __half* __restrict__ Bh,
    const float* __restrict__ bias, float* __restrict__ Cf)
{
    extern __shared__ char sm[];
    const uint32_t sbase = smem_u32(sm);
    const int tid = threadIdx.x;
    const int lane = tid & 31, wid = tid >> 5;
    const int wm = wid & 1, wn = wid >> 1;
    const int m0 = blockIdx.y * 128, n0 = blockIdx.x * 128;

    float acc[4][4][4];
#pragma unroll
    for (int i = 0; i < 4; i++)
#pragma unroll
        for (int j = 0; j < 4; j++)
#pragma unroll
            for (int k = 0; k < 4; k++) acc[i][j][k] = 0.f;

#define ISSUE_STAGE1(buf, k0)                                                  \
    do {                                                                       \
        const uint32_t st = sbase + (buf) * G1_STAGE;                          \
        _Pragma("unroll")                                                      \
        for (int c = 0; c < 4; c++) {                                          \
            const int idx = c * 256 + tid;                                     \
            const int row = idx >> 3, seg = idx & 7;                           \
            uint32_t off = (uint32_t)(row * 128 + seg * 16);                   \
            off ^= ((off >> 3) & 0x70);                                        \
            const size_t gaa = (size_t)(m0 + row) * 1024 + (k0) + seg * 8;     \
            const size_t gbb = (size_t)(n0 + row) * 1024 + (k0) + seg * 8;     \
            CP_ASYNC16(st + G1_AOFF + off, (const char*)(Ah + gaa));           \
            CP_ASYNC16(st + G1_BOFF + off, (const char*)(Bh + gbb));           \
        }                                                                      \
    } while (0)

    ISSUE_STAGE1(0, 0);
    CP_COMMIT();

    for (int s = 0; s < 16; s++) {
        if (s < 15) {
            ISSUE_STAGE1((s + 1) & 1, (s + 1) * 64);
            CP_COMMIT();
            CP_WAIT(1);
        } else {
            CP_WAIT(0);
        }
        __syncthreads();

        const uint32_t st = sbase + (s & 1) * G1_STAGE;
#pragma unroll
        for (int ks = 0; ks < 4; ks++) {
            uint32_t ah[4][4], bh[2][4];
            const int ar = (lane & 7) + ((lane >> 3) & 1) * 8;
            const int ak = ks * 16 + ((lane >> 4) & 1) * 8;
#pragma unroll
            for (int mt = 0; mt < 4; mt++) {
                uint32_t off = (uint32_t)((wm * 64 + mt * 16 + ar) * 128 + ak * 2);
                off ^= ((off >> 3) & 0x70);
                ldsm_x4(ah[mt], st + G1_AOFF + off);
            }
            const int bn = (lane & 7) + ((lane >> 4) & 1) * 8;
            const int bk = ks * 16 + ((lane >> 3) & 1) * 8;
#pragma unroll
            for (int np = 0; np < 2; np++) {
                uint32_t off = (uint32_t)((wn * 32 + np * 16 + bn) * 128 + bk * 2);
                off ^= ((off >> 3) & 0x70);
                ldsm_x4(bh[np], st + G1_BOFF + off);
            }
#pragma unroll
            for (int mt = 0; mt < 4; mt++)
#pragma unroll
                for (int nt = 0; nt < 4; nt++)
                    mma_f16(acc[mt][nt], ah[mt], &bh[nt >> 1][(nt & 1) * 2]);
        }
        __syncthreads();
    }
#undef ISSUE_STAGE1

#pragma unroll
    for (int mt = 0; mt < 4; mt++) {
        const int row = m0 + wm * 64 + mt * 16 + (lane >> 2);
#pragma unroll
        for (int nt = 0; nt < 4; nt++) {
            const int col = n0 + wn * 32 + nt * 8 + (lane & 3) * 2;
            const float bx = __ldg(bias + col), by = __ldg(bias + col + 1);
            *(float2*)(Cf + (size_t)row * 1024 + col) =
                make_float2(acc[mt][nt][0] + bx, acc[mt][nt][1] + by);
            *(float2*)(Cf + (size_t)(row + 8) * 1024 + col) =
                make_float2(acc[mt][nt][2] + bx, acc[mt][nt][3] + by);
        }
    }
}

// ----------------------------- MMA flash attention (fp16, 2-stage) ---------
#define ATT_KOFF  0
#define ATT_VOFF  8192
#define ATT_STAGE 16384
#define ATT_QOFF  (2*ATT_STAGE)          // 32768
#define ATT_SMEM  (ATT_QOFF + 8192)      // 40960

__global__ void __launch_bounds__(128) attn_mma_kernel(
    const __half* __restrict__ Q,
    const __half* __restrict__ K,
    const __half* __restrict__ V,
    __half* __restrict__ A)
{
    extern __shared__ char sm[];
    const uint32_t sb = smem_u32(sm);
    const int tid = threadIdx.x;
    const int lane = tid & 31, wid = tid >> 5;
    const int b = blockIdx.z, h = blockIdx.y;
    const int q0 = blockIdx.x * 64;

    const size_t qbase = ((size_t)(b * SEQQ + q0)) * EMBED + h * HDIM;
#pragma unroll
    for (int c = 0; c < 4; c++) {
        const int idx = c * 128 + tid;
        const int row = idx >> 3, seg = idx & 7;
        uint32_t off = (uint32_t)(row * 128 + seg * 16);
        off ^= ((off >> 3) & 0x70);
        CP_ASYNC16(sb + ATT_QOFF + off,
                   (const char*)(Q + qbase + (size_t)row * 1024 + seg * 8));
    }
    CP_COMMIT();

#define ISSUE_KV(buf, kt)                                                      \
    do {                                                                       \
        const uint32_t st_ = sb + (buf) * ATT_STAGE;                           \
        const size_t kb = ((size_t)(b * SEQK + (kt) * 64)) * EMBED + h * HDIM; \
        _Pragma("unroll")                                                      \
        for (int c = 0; c < 4; c++) {                                          \
            const int idx = c * 128 + tid;                                     \
            const int row = idx >> 3, seg = idx & 7;                           \
            uint32_t off = (uint32_t)(row * 128 + seg * 16);                   \
            off ^= ((off >> 3) & 0x70);                                        \
            const size_t g = kb + (size_t)row * 1024 + seg * 8;                \
            CP_ASYNC16(st_ + ATT_KOFF + off, (const char*)(K + g));            \
            CP_ASYNC16(st_ + ATT_VOFF + off, (const char*)(V + g));            \
        }                                                                      \
    } while (0)

    ISSUE_KV(0, 0);
    CP_COMMIT();
    CP_WAIT(1);
    __syncthreads();

    uint32_t qh[4][4];
    {
        const int ar = (lane & 7) + ((lane >> 3) & 1) * 8;
#pragma unroll
        for (int ks = 0; ks < 4; ks++) {
            const int ak = ks * 16 + ((lane >> 4) & 1) * 8;
            uint32_t off = (uint32_t)((wid * 16 + ar) * 128 + ak * 2);
            off ^= ((off >> 3) & 0x70);
            ldsm_x4(qh[ks], sb + ATT_QOFF + off);
        }
    }

    const uint32_t onefrag = ((lane >> 2) == 0) ? 0x3C003C00u : 0u;
    const uint32_t ones2[2] = { onefrag, onefrag };

    float m0 = -1e30f, m1 = -1e30f;
    float oacc[9][4];
#pragma unroll
    for (int nt = 0; nt < 9; nt++)
#pragma unroll
        for (int k = 0; k < 4; k++) oacc[nt][k] = 0.f;

    for (int kt = 0; kt < 32; kt++) {
        if (kt < 31) {
            ISSUE_KV((kt + 1) & 1, kt + 1);
            CP_COMMIT();
            CP_WAIT(1);
        } else {
            CP_WAIT(0);
        }
        __syncthreads();
        const uint32_t st = sb + (kt & 1) * ATT_STAGE;

        float sacc[8][4];
#pragma unroll
        for (int nt = 0; nt < 8; nt++)
#pragma unroll
            for (int k = 0; k < 4; k++) sacc[nt][k] = 0.f;

#pragma unroll
        for (int ks = 0; ks < 4; ks++) {
            uint32_t kh[4][4];
            const int bn = (lane & 7) + ((lane >> 4) & 1) * 8;
            const int bk = ks * 16 + ((lane >> 3) & 1) * 8;
#pragma unroll
            for (int g = 0; g < 4; g++) {
                uint32_t off = (uint32_t)((g * 16 + bn) * 128 + bk * 2);
                off ^= ((off >> 3) & 0x70);
                ldsm_x4(kh[g], st + ATT_KOFF + off);
            }
#pragma unroll
            for (int nt = 0; nt < 8; nt++)
                mma_f16(sacc[nt], qh[ks], &kh[nt >> 1][(nt & 1) * 2]);
        }

        float mx0 = sacc[0][0], mx1 = sacc[0][2];
#pragma unroll
        for (int nt = 0; nt < 8; nt++) {
            mx0 = fmaxf(mx0, fmaxf(sacc[nt][0], sacc[nt][1]));
            mx1 = fmaxf(mx1, fmaxf(sacc[nt][2], sacc[nt][3]));
        }
        mx0 = fmaxf(mx0, __shfl_xor_sync(0xffffffffu, mx0, 1));
        mx0 = fmaxf(mx0, __shfl_xor_sync(0xffffffffu, mx0, 2));
        mx1 = fmaxf(mx1, __shfl_xor_sync(0xffffffffu, mx1, 1));
        mx1 = fmaxf(mx1, __shfl_xor_sync(0xffffffffu, mx1, 2));
        const bool nochange = (mx0 <= m0) && (mx1 <= m1);
        const float mn0 = fmaxf(m0, mx0), mn1 = fmaxf(m1, mx1);

        if (__all_sync(0xffffffffu, nochange)) {
            m0 = mn0; m1 = mn1;
        } else {
            const float a0 = ex2f(m0 - mn0), a1 = ex2f(m1 - mn1);
            m0 = mn0; m1 = mn1;
#pragma unroll
            for (int nt = 0; nt < 9; nt++) {
                oacc[nt][0] *= a0; oacc[nt][1] *= a0;
                oacc[nt][2] *= a1; oacc[nt][3] *= a1;
            }
        }

        uint32_t ph[4][4];
#pragma unroll
        for (int kf = 0; kf < 4; kf++) {
            ph[kf][0] = ex2_h2(sacc[2*kf][0]   - m0, sacc[2*kf][1]   - m0);
            ph[kf][1] = ex2_h2(sacc[2*kf][2]   - m1, sacc[2*kf][3]   - m1);
            ph[kf][2] = ex2_h2(sacc[2*kf+1][0] - m0, sacc[2*kf+1][1] - m0);
            ph[kf][3] = ex2_h2(sacc[2*kf+1][2] - m1, sacc[2*kf+1][3] - m1);
        }

#pragma unroll
        for (int ks = 0; ks < 4; ks++) {
            uint32_t vh[4][4];
            const int vk = ((lane >> 3) & 1) * 8 + (lane & 7);
            const int vd = ((lane >> 4) & 1) * 8;
#pragma unroll
            for (int dp = 0; dp < 4; dp++) {
                uint32_t off = (uint32_t)((ks * 16 + vk) * 128 + (dp * 16 + vd) * 2);
                off ^= ((off >> 3) & 0x70);
                ldsm_x4_t(vh[dp], st + ATT_VOFF + off);
            }
#pragma unroll
            for (int nt = 0; nt < 8; nt++)
                mma_f16(oacc[nt], ph[ks], &vh[nt >> 1][(nt & 1) * 2]);
            mma_f16(oacc[8], ph[ks], ones2);
        }
        __syncthreads();
    }
#undef ISSUE_KV

    const int src = lane & ~3;
    const float l0 = __shfl_sync(0xffffffffu, oacc[8][0], src);
    const float l1 = __shfl_sync(0xffffffffu, oacc[8][2], src);

    const float inv0 = 1.f / l0, inv1 = 1.f / l1;
    const size_t row0 = (size_t)(b * SEQQ + q0 + wid * 16 + (lane >> 2));
    const size_t row1 = row0 + 8;
    const int colb = h * HDIM + (lane & 3) * 2;
#pragma unroll
    for (int nt = 0; nt < 8; nt++) {
        const int col = colb + nt * 8;
        *(uint32_t*)(A + row0 * 1024 + col) = pack_h2(oacc[nt][0] * inv0, oacc[nt][1] * inv0);
        *(uint32_t*)(A + row1 * 1024 + col) = pack_h2(oacc[nt][2] * inv1, oacc[nt][3] * inv1);
    }
}

// ---------------------------------------------------------------------------
extern "C" void kernel_launch(void* const* d_in, const int* in_sizes, int n_in,
                              void* d_out, int out_size)
{
    const float* Qin = (const float*)d_in[0];
    const float* Kin = (const float*)d_in[1];
    const float* Vin = (const float*)d_in[2];
    const float* Wq  = (const float*)d_in[3];
    const float* bq  = (const float*)d_in[4];
    const float* Wk  = (const float*)d_in[5];
    const float* bk  = (const float*)d_in[6];
    const float* Wv  = (const float*)d_in[7];
    const float* bv  = (const float*)d_in[8];
    const float* Wo  = (const float*)d_in[9];
    const float* bo  = (const float*)d_in[10];
    float* out = (float*)d_out;

    __half *xq,*xkH,*xkL,*xv;
    __half *wq,*wk,*wv,*wo;
    __half *q,*k,*v,*a;
    cudaGetSymbolAddress((void**)&xq,  g_Xq);
    cudaGetSymbolAddress((void**)&xkH, g_XkH); cudaGetSymbolAddress((void**)&xkL, g_XkL);
    cudaGetSymbolAddress((void**)&xv,  g_Xv);
    cudaGetSymbolAddress((void**)&wq, g_Wq); cudaGetSymbolAddress((void**)&wk, g_Wk);
    cudaGetSymbolAddress((void**)&wv, g_Wv); cudaGetSymbolAddress((void**)&wo, g_Wo);
    cudaGetSymbolAddress((void**)&q,  g_Q);  cudaGetSymbolAddress((void**)&k,  g_K);
    cudaGetSymbolAddress((void**)&v,  g_V);  cudaGetSymbolAddress((void**)&a,  g_A);

    cudaFuncSetAttribute(gemm_mma_kernel,  cudaFuncAttributeMaxDynamicSharedMemorySize, GB_SMEM);
    cudaFuncSetAttribute(gemm1_mma_kernel, cudaFuncAttributeMaxDynamicSharedMemorySize, G1_SMEM);
    cudaFuncSetAttribute(attn_mma_kernel,  cudaFuncAttributeMaxDynamicSharedMemorySize, ATT_SMEM);

    const int nAct4 = MROWS * EMBED / 4;   // 1048576
    const int nW4   = EMBED * EMBED / 4;   // 262144

    PrepJob p0 = { Qin, xq, nullptr, nAct4 };   // Q input plain fp16
    PrepJob p1 = { Kin, xkH, xkL, nAct4 };      // K input split (kept)
    PrepJob p2 = { Vin, xv, nullptr, nAct4 };
    PrepJob p3 = { Wq, wq, nullptr, nW4 };
    PrepJob p4 = { Wk, wk, nullptr, nW4 };
    PrepJob p5 = { Wv, wv, nullptr, nW4 };
    PrepJob p6 = { Wo, wo, nullptr, nW4 };
    dim3 prep_grid((nAct4 + 255) / 256, 7);
    prep_kernel<<<prep_grid, 256>>>(p0, p1, p2, p3, p4, p5, p6);

    const float qscale = 0.125f * 1.4426950408889634f;   // 1/sqrt(64) * log2(e)

    GemmArgs argQ = { xq,  nullptr, wq, bq, nullptr, q, qscale };   // 1-term
    GemmArgs argK = { xkH, xkL,     wk, bk, nullptr, k, 1.0f };     // 2-term
    GemmArgs argV = { xv,  nullptr, wv, bv, nullptr, v, 1.0f };     // 1-term

    dim3 qkv_grid(EMBED / 128, MROWS / 128, 3);   // (8, 32, 3)
    gemm_mma_kernel<<<qkv_grid, 256, GB_SMEM>>>(argQ, argK, argV);

    dim3 attn_grid(SEQQ / 64, NHEAD, BATCH);      // (32, 16, 2)
    attn_mma_kernel<<<attn_grid, 128, ATT_SMEM>>>(q, k, v, a);

    dim3 o_grid(EMBED / 128, MROWS / 128);        // (8, 32)
    gemm1_mma_kernel<<<o_grid, 256, G1_SMEM>>>(a, wo, bo, out);
}

// round 16
// speedup vs baseline: 1.0434x; 1.0198x over previous
#include <cuda_runtime.h>
#include <cuda_fp16.h>
#include <cstdint>
#include <math.h>

#define EMBED 1024
#define NHEAD 16
#define HDIM  64
#define BATCH 2
#define SEQQ  2048
#define SEQK  2048
#define MROWS (BATCH*SEQQ)   // 4096

// ----------------------------- scratch (no allocs allowed) -----------------
__device__ __half g_Xq [MROWS*EMBED];                       // Q input plain fp16
__device__ __half g_XkH[MROWS*EMBED], g_XkL[MROWS*EMBED];   // K input split
__device__ __half g_Xv [MROWS*EMBED];                       // V input plain fp16
__device__ __half g_Wq[EMBED*EMBED], g_Wk[EMBED*EMBED];     // plain fp16 weights
__device__ __half g_Wv[EMBED*EMBED], g_Wo[EMBED*EMBED];
__device__ __half g_Q [MROWS*EMBED];                        // plain fp16 activations
__device__ __half g_K [MROWS*EMBED];
__device__ __half g_V [MROWS*EMBED];
__device__ __half g_A [MROWS*EMBED];                        // attn out, plain fp16

// ----------------------------- helpers -------------------------------------
__device__ __forceinline__ uint32_t smem_u32(const void* p) {
    uint32_t a;
    asm("{ .reg .u64 t; cvta.to.shared.u64 t, %1; cvt.u32.u64 %0, t; }" : "=r"(a) : "l"(p));
    return a;
}
#define CP_ASYNC16(dst, src) \
    asm volatile("cp.async.cg.shared.global [%0], [%1], 16;" :: "r"(dst), "l"(src))
#define CP_COMMIT() asm volatile("cp.async.commit_group;" ::: "memory")
#define CP_WAIT(n)  asm volatile("cp.async.wait_group %0;" :: "n"(n) : "memory")

__device__ __forceinline__ void ldsm_x4(uint32_t* r, uint32_t addr) {
    asm volatile("ldmatrix.sync.aligned.m8n8.x4.shared.b16 {%0,%1,%2,%3}, [%4];"
        : "=r"(r[0]), "=r"(r[1]), "=r"(r[2]), "=r"(r[3]) : "r"(addr));
}
__device__ __forceinline__ void ldsm_x4_t(uint32_t* r, uint32_t addr) {
    asm volatile("ldmatrix.sync.aligned.m8n8.x4.trans.shared.b16 {%0,%1,%2,%3}, [%4];"
        : "=r"(r[0]), "=r"(r[1]), "=r"(r[2]), "=r"(r[3]) : "r"(addr));
}
__device__ __forceinline__ void mma_f16(float* c, const uint32_t* a, const uint32_t* b) {
    asm volatile(
        "mma.sync.aligned.m16n8k16.row.col.f32.f16.f16.f32 "
        "{%0,%1,%2,%3}, {%4,%5,%6,%7}, {%8,%9}, {%0,%1,%2,%3};"
        : "+f"(c[0]), "+f"(c[1]), "+f"(c[2]), "+f"(c[3])
        : "r"(a[0]), "r"(a[1]), "r"(a[2]), "r"(a[3]), "r"(b[0]), "r"(b[1]));
}
__device__ __forceinline__ float ex2f(float x) {
    float y; asm("ex2.approx.f32 %0, %1;" : "=f"(y) : "f"(x)); return y;
}
__device__ __forceinline__ uint32_t ex2_h2(float x, float y) {
    uint32_t h;
    asm("{\n\t.reg .b32 t;\n\t"
        "cvt.rn.f16x2.f32 t, %2, %1;\n\t"
        "ex2.approx.f16x2 %0, t;\n\t}"
        : "=r"(h) : "f"(x), "f"(y));
    return h;
}
__device__ __forceinline__ uint32_t pack_h2(float x, float y) {
    __half2 h = __float22half2_rn(make_float2(x, y));
    return *reinterpret_cast<uint32_t*>(&h);
}
__device__ __forceinline__ void split_pair_h(float x, float y, uint32_t& hi, uint32_t& lo) {
    __half2 h = __float22half2_rn(make_float2(x, y));
    float hx = __low2float(h), hy = __high2float(h);
    __half2 l = __float22half2_rn(make_float2(x - hx, y - hy));
    hi = *reinterpret_cast<uint32_t*>(&h);
    lo = *reinterpret_cast<uint32_t*>(&l);
}

// ----------------------------- fused conversions (flat grid, no idle) ------
struct PrepJob { const float* src; __half* hi; __half* lo; int n4; };
// blocks [0,4096) job0, [4096,8192) job1, [8192,12288) job2,
// then 4x1024 for weight jobs.
__global__ void prep_kernel(PrepJob j0, PrepJob j1, PrepJob j2, PrepJob j3,
                            PrepJob j4, PrepJob j5, PrepJob j6)
{
    int bid = blockIdx.x;
    PrepJob j;
    if      (bid < 4096)  { j = j0; }
    else if (bid < 8192)  { j = j1; bid -= 4096; }
    else if (bid < 12288) { j = j2; bid -= 8192; }
    else if (bid < 13312) { j = j3; bid -= 12288; }
    else if (bid < 14336) { j = j4; bid -= 13312; }
    else if (bid < 15360) { j = j5; bid -= 14336; }
    else                  { j = j6; bid -= 15360; }
    int i = bid * blockDim.x + threadIdx.x;
    if (i >= j.n4) return;
    float4 v = ((const float4*)j.src)[i];
    if (j.lo) {
        uint32_t h0, l0, h1, l1;
        split_pair_h(v.x, v.y, h0, l0);
        split_pair_h(v.z, v.w, h1, l1);
        ((uint32_t*)j.hi)[2*i] = h0; ((uint32_t*)j.hi)[2*i+1] = h1;
        ((uint32_t*)j.lo)[2*i] = l0; ((uint32_t*)j.lo)[2*i+1] = l1;
    } else {
        ((uint32_t*)j.hi)[2*i]   = pack_h2(v.x, v.y);
        ((uint32_t*)j.hi)[2*i+1] = pack_h2(v.z, v.w);
    }
}

// ----------------------------- HMMA GEMM (QKV batched) ---------------------
// 2-term A if Al != nullptr, else 1-term. Branches are block-uniform.
struct GemmArgs {
    const __half *Ah, *Al, *Bh;
    const float* bias;
    float* Cf;
    __half *Ch;
    float scale;
};

#define GB_AOFF  0
#define GB_ALOFF 16384
#define GB_BOFF  32768
#define GB_STAGE 49152
#define GB_SMEM  (2*GB_STAGE) // 98304

__global__ void __launch_bounds__(256, 2) gemm_mma_kernel(
    GemmArgs ga0, GemmArgs ga1, GemmArgs ga2)
{
    const GemmArgs g = (blockIdx.z == 0) ? ga0 : (blockIdx.z == 1) ? ga1 : ga2;
    const bool two = (g.Al != nullptr);

    extern __shared__ char sm[];
    const uint32_t sbase = smem_u32(sm);
    const int tid = threadIdx.x;
    const int lane = tid & 31, wid = tid >> 5;
    const int wm = wid & 1, wn = wid >> 1;
    const int m0 = blockIdx.y * 128, n0 = blockIdx.x * 128;

    float acc[4][4][4];
#pragma unroll
    for (int i = 0; i < 4; i++)
#pragma unroll
        for (int j = 0; j < 4; j++)
#pragma unroll
            for (int k = 0; k < 4; k++) acc[i][j][k] = 0.f;

#define ISSUE_STAGE(buf, k0)                                                   \
    do {                                                                       \
        const uint32_t st = sbase + (buf) * GB_STAGE;                          \
        _Pragma("unroll")                                                      \
        for (int c = 0; c < 4; c++) {                                          \
            const int idx = c * 256 + tid;                                     \
            const int row = idx >> 3, seg = idx & 7;                           \
            uint32_t off = (uint32_t)(row * 128 + seg * 16);                   \
            off ^= ((off >> 3) & 0x70);                                        \
            const size_t gaa = (size_t)(m0 + row) * 1024 + (k0) + seg * 8;     \
            const size_t gbb = (size_t)(n0 + row) * 1024 + (k0) + seg * 8;     \
            CP_ASYNC16(st + GB_AOFF + off,  (const char*)(g.Ah + gaa));        \
            if (two) CP_ASYNC16(st + GB_ALOFF + off, (const char*)(g.Al + gaa)); \
            CP_ASYNC16(st + GB_BOFF + off,  (const char*)(g.Bh + gbb));        \
        }                                                                      \
    } while (0)

    ISSUE_STAGE(0, 0);
    CP_COMMIT();

    for (int s = 0; s < 16; s++) {
        if (s < 15) {
            ISSUE_STAGE((s + 1) & 1, (s + 1) * 64);
            CP_COMMIT();
            CP_WAIT(1);
        } else {
            CP_WAIT(0);
        }
        __syncthreads();

        const uint32_t st = sbase + (s & 1) * GB_STAGE;
#pragma unroll
        for (int ks = 0; ks < 4; ks++) {
            uint32_t ah[4][4], al[4][4], bh[2][4];
            const int ar = (lane & 7) + ((lane >> 3) & 1) * 8;
            const int ak = ks * 16 + ((lane >> 4) & 1) * 8;
#pragma unroll
            for (int mt = 0; mt < 4; mt++) {
                uint32_t off = (uint32_t)((wm * 64 + mt * 16 + ar) * 128 + ak * 2);
                off ^= ((off >> 3) & 0x70);
                ldsm_x4(ah[mt], st + GB_AOFF + off);
                if (two) ldsm_x4(al[mt], st + GB_ALOFF + off);
            }
            const int bn = (lane & 7) + ((lane >> 4) & 1) * 8;
            const int bk = ks * 16 + ((lane >> 3) & 1) * 8;
#pragma unroll
            for (int np = 0; np < 2; np++) {
                uint32_t off = (uint32_t)((wn * 32 + np * 16 + bn) * 128 + bk * 2);
                off ^= ((off >> 3) & 0x70);
                ldsm_x4(bh[np], st + GB_BOFF + off);
            }
#pragma unroll
            for (int mt = 0; mt < 4; mt++) {
#pragma unroll
                for (int nt = 0; nt < 4; nt++) {
                    const uint32_t* bhf = &bh[nt >> 1][(nt & 1) * 2];
                    mma_f16(acc[mt][nt], ah[mt], bhf);
                    if (two) mma_f16(acc[mt][nt], al[mt], bhf);
                }
            }
        }
        __syncthreads();
    }
#undef ISSUE_STAGE

#pragma unroll
    for (int mt = 0; mt < 4; mt++) {
        const int row = m0 + wm * 64 + mt * 16 + (lane >> 2);
#pragma unroll
        for (int nt = 0; nt < 4; nt++) {
            const int col = n0 + wn * 32 + nt * 8 + (lane & 3) * 2;
            const float bx = __ldg(g.bias + col), by = __ldg(g.bias + col + 1);
            float v0 = (acc[mt][nt][0] + bx) * g.scale;
            float v1 = (acc[mt][nt][1] + by) * g.scale;
            float v2 = (acc[mt][nt][2] + bx) * g.scale;
            float v3 = (acc[mt][nt][3] + by) * g.scale;
            if (g.Cf) {
                *(float2*)(g.Cf + (size_t)row * 1024 + col)       = make_float2(v0, v1);
                *(float2*)(g.Cf + (size_t)(row + 8) * 1024 + col) = make_float2(v2, v3);
            } else {
                *(uint32_t*)(g.Ch + (size_t)row * 1024 + col)       = pack_h2(v0, v1);
                *(uint32_t*)(g.Ch + (size_t)(row + 8) * 1024 + col) = pack_h2(v2, v3);
            }
        }
    }
}

// ----------------------------- HMMA GEMM, 1-term A (Wo), 2-stage -----------
#define G1_AOFF  0
#define G1_BOFF  16384
#define G1_STAGE 32768
#define G1_SMEM  (2*G1_STAGE) // 65536

__global__ void __launch_bounds__(256, 2) gemm1_mma_kernel(
    const __half* __restrict__ Ah, const __half* __restrict__ Bh,
    const float* __restrict__ bias, float* __restrict__ Cf)
{
    extern __shared__ char sm[];
    const uint32_t sbase = smem_u32(sm);
    const int tid = threadIdx.x;
    const int lane = tid & 31, wid = tid >> 5;
    const int wm = wid & 1, wn = wid >> 1;
    const int m0 = blockIdx.y * 128, n0 = blockIdx.x * 128;

    float acc[4][4][4];
#pragma unroll
    for (int i = 0; i < 4; i++)
#pragma unroll
        for (int j = 0; j < 4; j++)
#pragma unroll
            for (int k = 0; k < 4; k++) acc[i][j][k] = 0.f;

#define ISSUE_STAGE1(buf, k0)                                                  \
    do {                                                                       \
        const uint32_t st = sbase + (buf) * G1_STAGE;                          \
        _Pragma("unroll")                                                      \
        for (int c = 0; c < 4; c++) {                                          \
            const int idx = c * 256 + tid;                                     \
            const int row = idx >> 3, seg = idx & 7;                           \
            uint32_t off = (uint32_t)(row * 128 + seg * 16);                   \
            off ^= ((off >> 3) & 0x70);                                        \
            const size_t gaa = (size_t)(m0 + row) * 1024 + (k0) + seg * 8;     \
            const size_t gbb = (size_t)(n0 + row) * 1024 + (k0) + seg * 8;     \
            CP_ASYNC16(st + G1_AOFF + off, (const char*)(Ah + gaa));           \
            CP_ASYNC16(st + G1_BOFF + off, (const char*)(Bh + gbb));           \
        }                                                                      \
    } while (0)

    ISSUE_STAGE1(0, 0);
    CP_COMMIT();

    for (int s = 0; s < 16; s++) {
        if (s < 15) {
            ISSUE_STAGE1((s + 1) & 1, (s + 1) * 64);
            CP_COMMIT();
            CP_WAIT(1);
        } else {
            CP_WAIT(0);
        }
        __syncthreads();

        const uint32_t st = sbase + (s & 1) * G1_STAGE;
#pragma unroll
        for (int ks = 0; ks < 4; ks++) {
            uint32_t ah[4][4], bh[2][4];
            const int ar = (lane & 7) + ((lane >> 3) & 1) * 8;
            const int ak = ks * 16 + ((lane >> 4) & 1) * 8;
#pragma unroll
            for (int mt = 0; mt < 4; mt++) {
                uint32_t off = (uint32_t)((wm * 64 + mt * 16 + ar) * 128 + ak * 2);
                off ^= ((off >> 3) & 0x70);
                ldsm_x4(ah[mt], st + G1_AOFF + off);
            }
            const int bn = (lane & 7) + ((lane >> 4) & 1) * 8;
            const int bk = ks * 16 + ((lane >> 3) & 1) * 8;
#pragma unroll
            for (int np = 0; np < 2; np++) {
                uint32_t off = (uint32_t)((wn * 32 + np * 16 + bn) * 128 + bk * 2);
                off ^= ((off >> 3) & 0x70);
                ldsm_x4(bh[np], st + G1_BOFF + off);
            }
#pragma unroll
            for (int mt = 0; mt < 4; mt++)
#pragma unroll
                for (int nt = 0; nt < 4; nt++)
                    mma_f16(acc[mt][nt], ah[mt], &bh[nt >> 1][(nt & 1) * 2]);
        }
        __syncthreads();
    }
#undef ISSUE_STAGE1

#pragma unroll
    for (int mt = 0; mt < 4; mt++) {
        const int row = m0 + wm * 64 + mt * 16 + (lane >> 2);
#pragma unroll
        for (int nt = 0; nt < 4; nt++) {
            const int col = n0 + wn * 32 + nt * 8 + (lane & 3) * 2;
            const float bx = __ldg(bias + col), by = __ldg(bias + col + 1);
            *(float2*)(Cf + (size_t)row * 1024 + col) =
                make_float2(acc[mt][nt][0] + bx, acc[mt][nt][1] + by);
            *(float2*)(Cf + (size_t)(row + 8) * 1024 + col) =
                make_float2(acc[mt][nt][2] + bx, acc[mt][nt][3] + by);
        }
    }
}

// ----------------------------- MMA flash attention (fp16, proven) ----------
#define ATT_KOFF  0
#define ATT_VOFF  8192
#define ATT_STAGE 16384
#define ATT_QOFF  (2*ATT_STAGE)          // 32768
#define ATT_SMEM  (ATT_QOFF + 8192)      // 40960

__global__ void __launch_bounds__(128) attn_mma_kernel(
    const __half* __restrict__ Q,
    const __half* __restrict__ K,
    const __half* __restrict__ V,
    __half* __restrict__ A)
{
    extern __shared__ char sm[];
    const uint32_t sb = smem_u32(sm);
    const int tid = threadIdx.x;
    const int lane = tid & 31, wid = tid >> 5;
    const int b = blockIdx.z, h = blockIdx.y;
    const int q0 = blockIdx.x * 64;

    const size_t qbase = ((size_t)(b * SEQQ + q0)) * EMBED + h * HDIM;
#pragma unroll
    for (int c = 0; c < 4; c++) {
        const int idx = c * 128 + tid;
        const int row = idx >> 3, seg = idx & 7;
        uint32_t off = (uint32_t)(row * 128 + seg * 16);
        off ^= ((off >> 3) & 0x70);
        CP_ASYNC16(sb + ATT_QOFF + off,
                   (const char*)(Q + qbase + (size_t)row * 1024 + seg * 8));
    }
    CP_COMMIT();

#define ISSUE_KV(buf, kt)                                                      \
    do {                                                                       \
        const uint32_t st_ = sb + (buf) * ATT_STAGE;                           \
        const size_t kb = ((size_t)(b * SEQK + (kt) * 64)) * EMBED + h * HDIM; \
        _Pragma("unroll")                                                      \
        for (int c = 0; c < 4; c++) {                                          \
            const int idx = c * 128 + tid;                                     \
            const int row = idx >> 3, seg = idx & 7;                           \
            uint32_t off = (uint32_t)(row * 128 + seg * 16);                   \
            off ^= ((off >> 3) & 0x70);                                        \
            const size_t g = kb + (size_t)row * 1024 + seg * 8;                \
            CP_ASYNC16(st_ + ATT_KOFF + off, (const char*)(K + g));            \
            CP_ASYNC16(st_ + ATT_VOFF + off, (const char*)(V + g));            \
        }                                                                      \
    } while (0)

    ISSUE_KV(0, 0);
    CP_COMMIT();
    CP_WAIT(1);
    __syncthreads();

    uint32_t qh[4][4];
    {
        const int ar = (lane & 7) + ((lane >> 3) & 1) * 8;
#pragma unroll
        for (int ks = 0; ks < 4; ks++) {
            const int ak = ks * 16 + ((lane >> 4) & 1) * 8;
            uint32_t off = (uint32_t)((wid * 16 + ar) * 128 + ak * 2);
            off ^= ((off >> 3) & 0x70);
            ldsm_x4(qh[ks], sb + ATT_QOFF + off);
        }
    }

    const uint32_t onefrag = ((lane >> 2) == 0) ? 0x3C003C00u : 0u;
    const uint32_t ones2[2] = { onefrag, onefrag };

    float m0 = -1e30f, m1 = -1e30f;
    float oacc[9][4];
#pragma unroll
    for (int nt = 0; nt < 9; nt++)
#pragma unroll
        for (int k = 0; k < 4; k++) oacc[nt][k] = 0.f;

    for (int kt = 0; kt < 32; kt++) {
        if (kt < 31) {
            ISSUE_KV((kt + 1) & 1, kt + 1);
            CP_COMMIT();
            CP_WAIT(1);
        } else {
            CP_WAIT(0);
        }
        __syncthreads();
        const uint32_t st = sb + (kt & 1) * ATT_STAGE;

        float sacc[8][4];
#pragma unroll
        for (int nt = 0; nt < 8; nt++)
#pragma unroll
            for (int k = 0; k < 4; k++) sacc[nt][k] = 0.f;

#pragma unroll
        for (int ks = 0; ks < 4; ks++) {
            uint32_t kh[4][4];
            const int bn = (lane & 7) + ((lane >> 4) & 1) * 8;
            const int bk = ks * 16 + ((lane >> 3) & 1) * 8;
#pragma unroll
            for (int g = 0; g < 4; g++) {
                uint32_t off = (uint32_t)((g * 16 + bn) * 128 + bk * 2);
                off ^= ((off >> 3) & 0x70);
                ldsm_x4(kh[g], st + ATT_KOFF + off);
            }
#pragma unroll
            for (int nt = 0; nt < 8; nt++)
                mma_f16(sacc[nt], qh[ks], &kh[nt >> 1][(nt & 1) * 2]);
        }

        float mx0 = sacc[0][0], mx1 = sacc[0][2];
#pragma unroll
        for (int nt = 0; nt < 8; nt++) {
            mx0 = fmaxf(mx0, fmaxf(sacc[nt][0], sacc[nt][1]));
            mx1 = fmaxf(mx1, fmaxf(sacc[nt][2], sacc[nt][3]));
        }
        mx0 = fmaxf(mx0, __shfl_xor_sync(0xffffffffu, mx0, 1));
        mx0 = fmaxf(mx0, __shfl_xor_sync(0xffffffffu, mx0, 2));
        mx1 = fmaxf(mx1, __shfl_xor_sync(0xffffffffu, mx1, 1));
        mx1 = fmaxf(mx1, __shfl_xor_sync(0xffffffffu, mx1, 2));
        const bool nochange = (mx0 <= m0) && (mx1 <= m1);
        const float mn0 = fmaxf(m0, mx0), mn1 = fmaxf(m1, mx1);

        if (__all_sync(0xffffffffu, nochange)) {
            m0 = mn0; m1 = mn1;
        } else {
            const float a0 = ex2f(m0 - mn0), a1 = ex2f(m1 - mn1);
            m0 = mn0; m1 = mn1;
#pragma unroll
            for (int nt = 0; nt < 9; nt++) {
                oacc[nt][0] *= a0; oacc[nt][1] *= a0;
                oacc[nt][2] *= a1; oacc[nt][3] *= a1;
            }
        }

        uint32_t ph[4][4];
#pragma unroll
        for (int kf = 0; kf < 4; kf++) {
            ph[kf][0] = ex2_h2(sacc[2*kf][0]   - m0, sacc[2*kf][1]   - m0);
            ph[kf][1] = ex2_h2(sacc[2*kf][2]   - m1, sacc[2*kf][3]   - m1);
            ph[kf][2] = ex2_h2(sacc[2*kf+1][0] - m0, sacc[2*kf+1][1] - m0);
            ph[kf][3] = ex2_h2(sacc[2*kf+1][2] - m1, sacc[2*kf+1][3] - m1);
        }

#pragma unroll
        for (int ks = 0; ks < 4; ks++) {
            uint32_t vh[4][4];
            const int vk = ((lane >> 3) & 1) * 8 + (lane & 7);
            const int vd = ((lane >> 4) & 1) * 8;
#pragma unroll
            for (int dp = 0; dp < 4; dp++) {
                uint32_t off = (uint32_t)((ks * 16 + vk) * 128 + (dp * 16 + vd) * 2);
                off ^= ((off >> 3) & 0x70);
                ldsm_x4_t(vh[dp], st + ATT_VOFF + off);
            }
#pragma unroll
            for (int nt = 0; nt < 8; nt++)
                mma_f16(oacc[nt], ph[ks], &vh[nt >> 1][(nt & 1) * 2]);
            mma_f16(oacc[8], ph[ks], ones2);
        }
        __syncthreads();
    }
#undef ISSUE_KV

    const int src = lane & ~3;
    const float l0 = __shfl_sync(0xffffffffu, oacc[8][0], src);
    const float l1 = __shfl_sync(0xffffffffu, oacc[8][2], src);

    const float inv0 = 1.f / l0, inv1 = 1.f / l1;
    const size_t row0 = (size_t)(b * SEQQ + q0 + wid * 16 + (lane >> 2));
    const size_t row1 = row0 + 8;
    const int colb = h * HDIM + (lane & 3) * 2;
#pragma unroll
    for (int nt = 0; nt < 8; nt++) {
        const int col = colb + nt * 8;
        *(uint32_t*)(A + row0 * 1024 + col) = pack_h2(oacc[nt][0] * inv0, oacc[nt][1] * inv0);
        *(uint32_t*)(A + row1 * 1024 + col) = pack_h2(oacc[nt][2] * inv1, oacc[nt][3] * inv1);
    }
}

// ---------------------------------------------------------------------------
extern "C" void kernel_launch(void* const* d_in, const int* in_sizes, int n_in,
                              void* d_out, int out_size)
{
    const float* Qin = (const float*)d_in[0];
    const float* Kin = (const float*)d_in[1];
    const float* Vin = (const float*)d_in[2];
    const float* Wq  = (const float*)d_in[3];
    const float* bq  = (const float*)d_in[4];
    const float* Wk  = (const float*)d_in[5];
    const float* bk  = (const float*)d_in[6];
    const float* Wv  = (const float*)d_in[7];
    const float* bv  = (const float*)d_in[8];
    const float* Wo  = (const float*)d_in[9];
    const float* bo  = (const float*)d_in[10];
    float* out = (float*)d_out;

    __half *xq,*xkH,*xkL,*xv;
    __half *wq,*wk,*wv,*wo;
    __half *q,*k,*v,*a;
    cudaGetSymbolAddress((void**)&xq,  g_Xq);
    cudaGetSymbolAddress((void**)&xkH, g_XkH); cudaGetSymbolAddress((void**)&xkL, g_XkL);
    cudaGetSymbolAddress((void**)&xv,  g_Xv);
    cudaGetSymbolAddress((void**)&wq, g_Wq); cudaGetSymbolAddress((void**)&wk, g_Wk);
    cudaGetSymbolAddress((void**)&wv, g_Wv); cudaGetSymbolAddress((void**)&wo, g_Wo);
    cudaGetSymbolAddress((void**)&q,  g_Q);  cudaGetSymbolAddress((void**)&k,  g_K);
    cudaGetSymbolAddress((void**)&v,  g_V);  cudaGetSymbolAddress((void**)&a,  g_A);

    cudaFuncSetAttribute(gemm_mma_kernel,  cudaFuncAttributeMaxDynamicSharedMemorySize, GB_SMEM);
    cudaFuncSetAttribute(gemm1_mma_kernel, cudaFuncAttributeMaxDynamicSharedMemorySize, G1_SMEM);
    cudaFuncSetAttribute(attn_mma_kernel,  cudaFuncAttributeMaxDynamicSharedMemorySize, ATT_SMEM);

    const int nAct4 = MROWS * EMBED / 4;   // 1048576
    const int nW4   = EMBED * EMBED / 4;   // 262144

    PrepJob p0 = { Qin, xq, nullptr, nAct4 };
    PrepJob p1 = { Kin, xkH, xkL, nAct4 };
    PrepJob p2 = { Vin, xv, nullptr, nAct4 };
    PrepJob p3 = { Wq, wq, nullptr, nW4 };
    PrepJob p4 = { Wk, wk, nullptr, nW4 };
    PrepJob p5 = { Wv, wv, nullptr, nW4 };
    PrepJob p6 = { Wo, wo, nullptr, nW4 };
    // 3*4096 activation blocks + 4*1024 weight blocks = 16384, no idle blocks
    prep_kernel<<<16384, 256>>>(p0, p1, p2, p3, p4, p5, p6);

    const float qscale = 0.125f * 1.4426950408889634f;   // 1/sqrt(64) * log2(e)

    GemmArgs argQ = { xq,  nullptr, wq, bq, nullptr, q, qscale };   // 1-term
    GemmArgs argK = { xkH, xkL,     wk, bk, nullptr, k, 1.0f };     // 2-term
    GemmArgs argV = { xv,  nullptr, wv, bv, nullptr, v, 1.0f };     // 1-term

    // K (2-term, slow) at z=0 so wave 1 is homogeneous-slow and the
    // trailing waves contain only 1-term blocks (shorter tail).
    dim3 qkv_grid(EMBED / 128, MROWS / 128, 3);   // (8, 32, 3)
    gemm_mma_kernel<<<qkv_grid, 256, GB_SMEM>>>(argK, argQ, argV);

    dim3 attn_grid(SEQQ / 64, NHEAD, BATCH);      // (32, 16, 2)
    attn_mma_kernel<<<attn_grid, 128, ATT_SMEM>>>(q, k, v, a);

    dim3 o_grid(EMBED / 128, MROWS / 128);        // (8, 32)
    gemm1_mma_kernel<<<o_grid, 256, G1_SMEM>>>(a, wo, bo, out);
}